// round 1
// baseline (speedup 1.0000x reference)
#include <cuda_runtime.h>
#include <cuda_bf16.h>
#include <math.h>

#define B_   2
#define T_   2048
#define C_   1024
#define H_   16
#define DK_  64
#define HD_  1024   // H_*DK_
#define M_   4096   // B_*T_
#define SQRT_DK 8.0f

// ---------------- scratch (no allocation allowed) ----------------
__device__ float g_q[(size_t)B_*H_*T_*DK_];
__device__ float g_k[(size_t)B_*H_*T_*DK_];
__device__ float g_v[(size_t)B_*H_*T_*DK_];
__device__ float g_o[(size_t)B_*T_*HD_];

// ---------------- SGEMM: C[M,N] = A[M,K] * B[K,N] ----------------
// BM=128, BN=128, BK=16, TM=TN=8, 256 threads.
// scatter=1: output index (row=b*T+t, col=h*DK+d) -> [B,H,T,DK]
#define BM 128
#define BN 128
#define BK 16
#define TM 8
#define TN 8

__global__ __launch_bounds__(256, 2)
void sgemm_kernel(const float* __restrict__ A,
                  const float* __restrict__ Bm,
                  float* __restrict__ Cout,
                  int M, int N, int K, int scatter)
{
    __shared__ float As[BK][BM];
    __shared__ float Bs[BK][BN];

    const int tid  = threadIdx.x;
    const int bRow = blockIdx.y;
    const int bCol = blockIdx.x;

    const float* Ab = A  + (size_t)bRow * BM * K;
    const float* Bb = Bm + (size_t)bCol * BN;

    const int tRow = tid / 16;     // 0..15
    const int tCol = tid % 16;     // 0..15

    float acc[TM][TN];
#pragma unroll
    for (int i = 0; i < TM; i++)
#pragma unroll
        for (int j = 0; j < TN; j++) acc[i][j] = 0.0f;

    float regM[TM], regN[TN];

    for (int k0 = 0; k0 < K; k0 += BK) {
        // load A tile (128 x 16) transposed into As: 512 float4, 2 per thread
#pragma unroll
        for (int l = 0; l < 2; l++) {
            int idx = l * 256 + tid;
            int r = idx >> 2;              // 0..127
            int c = (idx & 3) * 4;         // 0,4,8,12
            float4 av = *(const float4*)(Ab + (size_t)r * K + k0 + c);
            As[c + 0][r] = av.x;
            As[c + 1][r] = av.y;
            As[c + 2][r] = av.z;
            As[c + 3][r] = av.w;
        }
        // load B tile (16 x 128): 512 float4, 2 per thread
#pragma unroll
        for (int l = 0; l < 2; l++) {
            int idx = l * 256 + tid;
            int r = idx >> 5;              // 0..15
            int c = (idx & 31) * 4;        // 0..124
            *(float4*)(&Bs[r][c]) = *(const float4*)(Bb + (size_t)(k0 + r) * N + c);
        }
        __syncthreads();

#pragma unroll
        for (int d = 0; d < BK; d++) {
#pragma unroll
            for (int i = 0; i < TM; i++) regM[i] = As[d][tRow * TM + i];
#pragma unroll
            for (int j = 0; j < TN; j++) regN[j] = Bs[d][tCol * TN + j];
#pragma unroll
            for (int i = 0; i < TM; i++)
#pragma unroll
                for (int j = 0; j < TN; j++)
                    acc[i][j] = fmaf(regM[i], regN[j], acc[i][j]);
        }
        __syncthreads();
    }

    // epilogue
#pragma unroll
    for (int i = 0; i < TM; i++) {
        int row = bRow * BM + tRow * TM + i;
#pragma unroll
        for (int j = 0; j < TN; j += 4) {
            int col = bCol * BN + tCol * TN + j;
            float4 v = make_float4(acc[i][j], acc[i][j+1], acc[i][j+2], acc[i][j+3]);
            if (scatter) {
                int b = row / T_, t = row % T_;
                int h = col / DK_, d = col % DK_;
                float* dst = Cout + (((size_t)(b * H_ + h) * T_ + t) * DK_ + d);
                *(float4*)dst = v;
            } else {
                *(float4*)(Cout + (size_t)row * N + col) = v;
            }
        }
    }
}

// ---------------- flash attention fp32 (causal, scale = *8) ----------------
// Block: 256 threads = 16x16, 64 query rows x 64 key cols per tile.
#define FR 64
#define FC 64
#define FPAD 65

__global__ __launch_bounds__(256, 3)
void flash_kernel(const float* __restrict__ q,
                  const float* __restrict__ k,
                  const float* __restrict__ v,
                  float* __restrict__ o)
{
    extern __shared__ float sm[];
    float* Qs = sm;                    // [64][65]
    float* Ks = Qs + FR * FPAD;        // [64][65]
    float* Vs = Ks + FC * FPAD;        // [64][65]
    float* Ps = Vs + FC * FPAD;        // [64][65]

    const int qt = blockIdx.x;         // query tile 0..31
    const int bh = blockIdx.y;         // 0..31
    const int b  = bh / H_;
    const int h  = bh % H_;

    const float* qb = q + (size_t)bh * T_ * DK_;
    const float* kb = k + (size_t)bh * T_ * DK_;
    const float* vb = v + (size_t)bh * T_ * DK_;

    const int tid = threadIdx.x;
    const int ty  = tid / 16;          // row group 0..15
    const int tx  = tid % 16;          // col group 0..15
    const int i0  = qt * FR;

    // load Q tile
#pragma unroll
    for (int l = 0; l < 4; l++) {
        int idx = l * 256 + tid;
        int r = idx >> 4;
        int c = (idx & 15) * 4;
        float4 t4 = *(const float4*)(qb + (size_t)(i0 + r) * DK_ + c);
        Qs[r * FPAD + c + 0] = t4.x;
        Qs[r * FPAD + c + 1] = t4.y;
        Qs[r * FPAD + c + 2] = t4.z;
        Qs[r * FPAD + c + 3] = t4.w;
    }

    float m_i[4], l_i[4], o_acc[4][4];
#pragma unroll
    for (int i = 0; i < 4; i++) {
        m_i[i] = -1e30f;
        l_i[i] = 0.0f;
#pragma unroll
        for (int j = 0; j < 4; j++) o_acc[i][j] = 0.0f;
    }

    for (int jt = 0; jt <= qt; jt++) {
        const int j0 = jt * FC;
        // load K,V tiles
#pragma unroll
        for (int l = 0; l < 4; l++) {
            int idx = l * 256 + tid;
            int r = idx >> 4;
            int c = (idx & 15) * 4;
            float4 kv4 = *(const float4*)(kb + (size_t)(j0 + r) * DK_ + c);
            Ks[r * FPAD + c + 0] = kv4.x;
            Ks[r * FPAD + c + 1] = kv4.y;
            Ks[r * FPAD + c + 2] = kv4.z;
            Ks[r * FPAD + c + 3] = kv4.w;
            float4 vv4 = *(const float4*)(vb + (size_t)(j0 + r) * DK_ + c);
            Vs[r * FPAD + c + 0] = vv4.x;
            Vs[r * FPAD + c + 1] = vv4.y;
            Vs[r * FPAD + c + 2] = vv4.z;
            Vs[r * FPAD + c + 3] = vv4.w;
        }
        __syncthreads();

        // S = Q K^T
        float s[4][4];
#pragma unroll
        for (int i = 0; i < 4; i++)
#pragma unroll
            for (int j = 0; j < 4; j++) s[i][j] = 0.0f;

#pragma unroll 4
        for (int d = 0; d < DK_; d++) {
            float qr[4], kr[4];
#pragma unroll
            for (int i = 0; i < 4; i++) qr[i] = Qs[(ty * 4 + i) * FPAD + d];
#pragma unroll
            for (int j = 0; j < 4; j++) kr[j] = Ks[(tx * 4 + j) * FPAD + d];
#pragma unroll
            for (int i = 0; i < 4; i++)
#pragma unroll
                for (int j = 0; j < 4; j++)
                    s[i][j] = fmaf(qr[i], kr[j], s[i][j]);
        }

        // scale (reference MULTIPLIES by sqrt(dk)) + causal mask on diag tile
#pragma unroll
        for (int i = 0; i < 4; i++)
#pragma unroll
            for (int j = 0; j < 4; j++) {
                s[i][j] *= SQRT_DK;
                if (jt == qt) {
                    int rg = i0 + ty * 4 + i;
                    int cg = j0 + tx * 4 + j;
                    if (cg > rg) s[i][j] = -1e30f;
                }
            }

        // online softmax per row
#pragma unroll
        for (int i = 0; i < 4; i++) {
            float mn = s[i][0];
#pragma unroll
            for (int j = 1; j < 4; j++) mn = fmaxf(mn, s[i][j]);
#pragma unroll
            for (int off = 8; off >= 1; off >>= 1)
                mn = fmaxf(mn, __shfl_xor_sync(0xffffffffu, mn, off, 16));

            float mnew = fmaxf(m_i[i], mn);
            float corr = expf(m_i[i] - mnew);
            m_i[i] = mnew;

            float rs = 0.0f;
#pragma unroll
            for (int j = 0; j < 4; j++) {
                float p = expf(s[i][j] - mnew);
                Ps[(ty * 4 + i) * FPAD + tx * 4 + j] = p;
                rs += p;
            }
#pragma unroll
            for (int off = 8; off >= 1; off >>= 1)
                rs += __shfl_xor_sync(0xffffffffu, rs, off, 16);

            l_i[i] = l_i[i] * corr + rs;
#pragma unroll
            for (int j = 0; j < 4; j++) o_acc[i][j] *= corr;
        }
        __syncthreads();

        // O += P * V   (thread owns rows ty*4.., d-cols tx*4..)
#pragma unroll 4
        for (int jj = 0; jj < FC; jj++) {
            float vv[4];
#pragma unroll
            for (int j = 0; j < 4; j++) vv[j] = Vs[jj * FPAD + tx * 4 + j];
#pragma unroll
            for (int i = 0; i < 4; i++) {
                float p = Ps[(ty * 4 + i) * FPAD + jj];
#pragma unroll
                for (int j = 0; j < 4; j++)
                    o_acc[i][j] = fmaf(p, vv[j], o_acc[i][j]);
            }
        }
        __syncthreads();
    }

    // write O in [B, T, H*DK] layout
#pragma unroll
    for (int i = 0; i < 4; i++) {
        float inv = 1.0f / l_i[i];
        int t = i0 + ty * 4 + i;
        float4 r4 = make_float4(o_acc[i][0] * inv, o_acc[i][1] * inv,
                                o_acc[i][2] * inv, o_acc[i][3] * inv);
        *(float4*)(o + (size_t)(b * T_ + t) * HD_ + h * DK_ + tx * 4) = r4;
    }
}

// ---------------- launch ----------------
extern "C" void kernel_launch(void* const* d_in, const int* in_sizes, int n_in,
                              void* d_out, int out_size)
{
    const float* x  = (const float*)d_in[0];
    const float* qm = (const float*)d_in[1];
    const float* km = (const float*)d_in[2];
    const float* vm = (const float*)d_in[3];
    const float* wm = (const float*)d_in[4];
    float* out = (float*)d_out;

    float *pq, *pk, *pv, *po;
    cudaGetSymbolAddress((void**)&pq, g_q);
    cudaGetSymbolAddress((void**)&pk, g_k);
    cudaGetSymbolAddress((void**)&pv, g_v);
    cudaGetSymbolAddress((void**)&po, g_o);

    const int smem = 4 * FR * FPAD * (int)sizeof(float);
    cudaFuncSetAttribute(flash_kernel, cudaFuncAttributeMaxDynamicSharedMemorySize, smem);

    dim3 gemmGrid(HD_ / BN, M_ / BM);   // (8, 32)

    // QKV projections with scatter to [B,H,T,DK]
    sgemm_kernel<<<gemmGrid, 256>>>(x, qm, pq, M_, HD_, C_, 1);
    sgemm_kernel<<<gemmGrid, 256>>>(x, km, pk, M_, HD_, C_, 1);
    sgemm_kernel<<<gemmGrid, 256>>>(x, vm, pv, M_, HD_, C_, 1);

    // fused causal attention -> [B,T,H*DK]
    dim3 flashGrid(T_ / FR, B_ * H_);   // (32, 32)
    flash_kernel<<<flashGrid, 256, smem>>>(pq, pk, pv, po);

    // output projection
    sgemm_kernel<<<gemmGrid, 256>>>(po, wm, out, M_, HD_, C_, 0);
}